// round 6
// baseline (speedup 1.0000x reference)
#include <cuda_runtime.h>
#include <cstdint>

// Cumulative accumulators: [0]=sum(d^2), [1..5]=T0..T4, [6..10]=C0..C4
__device__ double g_acc[11];
__device__ unsigned int g_ticket;

#define BLOCKS_PER_SM 4
#define GRID (148 * BLOCKS_PER_SM)   // 592
#define TPB  256
#define STAGE_ELEMS 2048
#define STAGE_BYTES (STAGE_ELEMS * 4)
#define NSTAGE 3
#define SMEM_DYN (NSTAGE * STAGE_BYTES * 2)   // 48 KB

#define MBARRIER_INIT(addr, count) \
    asm volatile("mbarrier.init.shared.b64 [%0], %1;" :: "r"(addr), "r"(count) : "memory")

#define MBARRIER_EXPECT_TX(addr, bytes) \
    asm volatile("mbarrier.arrive.expect_tx.shared.b64 _, [%0], %1;" :: "r"(addr), "r"(bytes) : "memory")

#define BULK_G2S(dst_smem, src_gmem, bytes, mbar) \
    asm volatile("cp.async.bulk.shared::cluster.global.mbarrier::complete_tx::bytes [%0], [%1], %2, [%3];" \
                 :: "r"(dst_smem), "l"(src_gmem), "r"(bytes), "r"(mbar) : "memory")

// HW-sleep try_wait (suspends instead of spinning)
#define MBARRIER_WAIT_PARITY(addr, parity) do {                                   \
    uint32_t _mbar = (addr);                                                      \
    uint32_t _par  = (parity);                                                    \
    asm volatile(                                                                 \
        "{\n\t"                                                                   \
        ".reg .pred P1;\n\t"                                                      \
        "WAIT_LOOP_%=:\n\t"                                                       \
        "mbarrier.try_wait.parity.shared.b64 P1, [%0], %1, 0x989680;\n\t"         \
        "@P1 bra.uni WAIT_DONE_%=;\n\t"                                           \
        "bra.uni WAIT_LOOP_%=;\n\t"                                               \
        "WAIT_DONE_%=:\n\t"                                                       \
        "}"                                                                       \
        :: "r"(_mbar), "r"(_par) : "memory");                                     \
} while (0)

// Packed pair processing: elements (a,b). Weights w_k = (t>=q_k)&(t<=q5) as 0/1
// floats; per bin one fma.f32x2 for T_k and one add.f32x2 for C_k.
__device__ __forceinline__ void pr_pair(float pa, float pb, float ta, float tb,
                                        float q0, float q1, float q2,
                                        float q3, float q4, float q5,
                                        unsigned long long& mse2,
                                        unsigned long long& T0, unsigned long long& T1,
                                        unsigned long long& T2, unsigned long long& T3,
                                        unsigned long long& T4,
                                        unsigned long long& C0, unsigned long long& C1,
                                        unsigned long long& C2, unsigned long long& C3,
                                        unsigned long long& C4)
{
    const unsigned long long NEG1X2 = 0xBF800000BF800000ull;  // (-1.0f, -1.0f)
    unsigned long long p2, t2, d2;
    asm("mov.b64 %0, {%1, %2};" : "=l"(p2) : "f"(pa), "f"(pb));
    asm("mov.b64 %0, {%1, %2};" : "=l"(t2) : "f"(ta), "f"(tb));
    asm("fma.rn.f32x2 %0, %1, %2, %3;" : "=l"(d2) : "l"(t2), "l"(NEG1X2), "l"(p2));
    asm("fma.rn.f32x2 %0, %1, %1, %0;" : "+l"(mse2) : "l"(d2));

    asm("{\n\t"
        ".reg .pred ha, hb;\n\t"
        ".reg .f32 wa, wb;\n\t"
        ".reg .b64 w2;\n\t"
        "setp.le.f32 ha, %12, %16;\n\t"                 // ta <= q5
        "setp.le.f32 hb, %13, %16;\n\t"                 // tb <= q5
        // bin cum 0
        "set.ge.and.f32.f32 wa, %12, %17, ha;\n\t"
        "set.ge.and.f32.f32 wb, %13, %17, hb;\n\t"
        "mov.b64 w2, {wa, wb};\n\t"
        "fma.rn.f32x2 %0, w2, %14, %0;\n\t"
        "add.rn.f32x2 %5, %5, w2;\n\t"
        // bin cum 1
        "set.ge.and.f32.f32 wa, %12, %18, ha;\n\t"
        "set.ge.and.f32.f32 wb, %13, %18, hb;\n\t"
        "mov.b64 w2, {wa, wb};\n\t"
        "fma.rn.f32x2 %1, w2, %14, %1;\n\t"
        "add.rn.f32x2 %6, %6, w2;\n\t"
        // bin cum 2
        "set.ge.and.f32.f32 wa, %12, %19, ha;\n\t"
        "set.ge.and.f32.f32 wb, %13, %19, hb;\n\t"
        "mov.b64 w2, {wa, wb};\n\t"
        "fma.rn.f32x2 %2, w2, %14, %2;\n\t"
        "add.rn.f32x2 %7, %7, w2;\n\t"
        // bin cum 3
        "set.ge.and.f32.f32 wa, %12, %20, ha;\n\t"
        "set.ge.and.f32.f32 wb, %13, %20, hb;\n\t"
        "mov.b64 w2, {wa, wb};\n\t"
        "fma.rn.f32x2 %3, w2, %14, %3;\n\t"
        "add.rn.f32x2 %8, %8, w2;\n\t"
        // bin cum 4
        "set.ge.and.f32.f32 wa, %12, %21, ha;\n\t"
        "set.ge.and.f32.f32 wb, %13, %21, hb;\n\t"
        "mov.b64 w2, {wa, wb};\n\t"
        "fma.rn.f32x2 %4, w2, %14, %4;\n\t"
        "add.rn.f32x2 %9, %9, w2;\n\t"
        "}"
        : "+l"(T0), "+l"(T1), "+l"(T2), "+l"(T3), "+l"(T4),
          "+l"(C0), "+l"(C1), "+l"(C2), "+l"(C3), "+l"(C4)
        : "l"(p2) /*%10 unused keepalive*/, "l"(t2) /*%11 unused*/,
          "f"(ta), "f"(tb), "l"(d2), "l"(NEG1X2) /*%15 unused*/,
          "f"(q5), "f"(q0), "f"(q1), "f"(q2), "f"(q3), "f"(q4));
}

__device__ __forceinline__ float pair_sum(unsigned long long v) {
    float lo, hi;
    asm("mov.b64 {%0, %1}, %2;" : "=f"(lo), "=f"(hi) : "l"(v));
    return lo + hi;
}

__global__ void __launch_bounds__(TPB, BLOCKS_PER_SM)
fused_loss_kernel(const float* __restrict__ y_pred,
                  const float* __restrict__ y_true,
                  const float* __restrict__ quants,
                  float* __restrict__ out, int n)
{
    extern __shared__ float smem[];
    float* sp = smem;                          // [NSTAGE][STAGE_ELEMS]
    float* st = smem + NSTAGE * STAGE_ELEMS;   // [NSTAGE][STAGE_ELEMS]
    __shared__ alignas(8) unsigned long long mbar[NSTAGE];
    __shared__ float shred[TPB / 32][11];

    const float q0 = quants[0], q1 = quants[1], q2 = quants[2];
    const float q3 = quants[3], q4 = quants[4], q5 = quants[5];

    unsigned long long mse2 = 0, T0 = 0, T1 = 0, T2 = 0, T3 = 0, T4 = 0;
    unsigned long long C0 = 0, C1 = 0, C2 = 0, C3 = 0, C4 = 0;

    const int tid = threadIdx.x;
    const int bid = blockIdx.x;

    uint32_t mb[NSTAGE];
#pragma unroll
    for (int s = 0; s < NSTAGE; s++)
        mb[s] = (uint32_t)__cvta_generic_to_shared(&mbar[s]);

    const int stages_total = n / STAGE_ELEMS;
    const int nst = (bid < stages_total) ? (stages_total - bid + GRID - 1) / GRID : 0;

    if (tid == 0) {
#pragma unroll
        for (int s = 0; s < NSTAGE; s++) MBARRIER_INIT(mb[s], 1);
    }
    __syncthreads();

    if (tid == 0) {
#pragma unroll
        for (int s = 0; s < NSTAGE; s++) {
            if (s < nst) {
                size_t off = ((size_t)bid + (size_t)s * GRID) * STAGE_ELEMS;
                MBARRIER_EXPECT_TX(mb[s], 2 * STAGE_BYTES);
                BULK_G2S((uint32_t)__cvta_generic_to_shared(sp + s * STAGE_ELEMS),
                         y_pred + off, STAGE_BYTES, mb[s]);
                BULK_G2S((uint32_t)__cvta_generic_to_shared(st + s * STAGE_ELEMS),
                         y_true + off, STAGE_BYTES, mb[s]);
            }
        }
    }

    int slot = 0, phase = 0;
    for (int j = 0; j < nst; j++) {
        MBARRIER_WAIT_PARITY(mb[slot], phase);

        const float4* __restrict__ pp = (const float4*)(sp + slot * STAGE_ELEMS);
        const float4* __restrict__ tt = (const float4*)(st + slot * STAGE_ELEMS);

        float4 Pa = pp[tid];
        float4 Ta = tt[tid];
        pr_pair(Pa.x, Pa.y, Ta.x, Ta.y, q0, q1, q2, q3, q4, q5,
                mse2, T0, T1, T2, T3, T4, C0, C1, C2, C3, C4);
        pr_pair(Pa.z, Pa.w, Ta.z, Ta.w, q0, q1, q2, q3, q4, q5,
                mse2, T0, T1, T2, T3, T4, C0, C1, C2, C3, C4);

        float4 Pb = pp[tid + TPB];
        float4 Tb = tt[tid + TPB];
        pr_pair(Pb.x, Pb.y, Tb.x, Tb.y, q0, q1, q2, q3, q4, q5,
                mse2, T0, T1, T2, T3, T4, C0, C1, C2, C3, C4);
        pr_pair(Pb.z, Pb.w, Tb.z, Tb.w, q0, q1, q2, q3, q4, q5,
                mse2, T0, T1, T2, T3, T4, C0, C1, C2, C3, C4);

        __syncthreads();  // everyone done reading this slot

        if (tid == 0 && (j + NSTAGE) < nst) {
            size_t off = ((size_t)bid + (size_t)(j + NSTAGE) * GRID) * STAGE_ELEMS;
            MBARRIER_EXPECT_TX(mb[slot], 2 * STAGE_BYTES);
            BULK_G2S((uint32_t)__cvta_generic_to_shared(sp + slot * STAGE_ELEMS),
                     y_pred + off, STAGE_BYTES, mb[slot]);
            BULK_G2S((uint32_t)__cvta_generic_to_shared(st + slot * STAGE_ELEMS),
                     y_true + off, STAGE_BYTES, mb[slot]);
        }

        if (++slot == NSTAGE) { slot = 0; phase ^= 1; }
    }

    // unpack packed accumulators
    float mse = pair_sum(mse2);
    float t0 = pair_sum(T0), t1 = pair_sum(T1), t2v = pair_sum(T2),
          t3 = pair_sum(T3), t4 = pair_sum(T4);
    float c0 = pair_sum(C0), c1 = pair_sum(C1), c2 = pair_sum(C2),
          c3 = pair_sum(C3), c4 = pair_sum(C4);

    // scalar tail (n % STAGE_ELEMS)
    for (int j = stages_total * STAGE_ELEMS + bid * TPB + tid; j < n; j += GRID * TPB) {
        float p = y_pred[j];
        float t = y_true[j];
        float d = p - t;
        mse = fmaf(d, d, mse);
        bool hi = (t <= q5);
        if ((t >= q0) & hi) { t0 += d; c0 += 1.0f; }
        if ((t >= q1) & hi) { t1 += d; c1 += 1.0f; }
        if ((t >= q2) & hi) { t2v += d; c2 += 1.0f; }
        if ((t >= q3) & hi) { t3 += d; c3 += 1.0f; }
        if ((t >= q4) & hi) { t4 += d; c4 += 1.0f; }
    }

    // ---- block reduction of 11 partials ----
    float v[11] = {mse, t0, t1, t2v, t3, t4, c0, c1, c2, c3, c4};
#pragma unroll
    for (int k = 0; k < 11; k++) {
#pragma unroll
        for (int off = 16; off > 0; off >>= 1)
            v[k] += __shfl_down_sync(0xFFFFFFFFu, v[k], off);
    }

    const int wid = tid >> 5;
    const int lid = tid & 31;
    if (lid == 0) {
#pragma unroll
        for (int k = 0; k < 11; k++) shred[wid][k] = v[k];
    }
    __syncthreads();

    if (tid < 11) {
        float acc = 0.0f;
#pragma unroll
        for (int w = 0; w < TPB / 32; w++) acc += shred[w][tid];
        atomicAdd(&g_acc[tid], (double)acc);
    }

    // ---- last block finalizes and resets (graph-replay safe) ----
    __syncthreads();
    if (tid == 0) {
        __threadfence();
        unsigned int ticket = atomicAdd(&g_ticket, 1u);
        if (ticket == GRID - 1) {
            double A[11];
#pragma unroll
            for (int k = 0; k < 11; k++) A[k] = atomicAdd(&g_acc[k], 0.0);

            double mse_d = A[0] / (double)n;
            double m = 0.0;
#pragma unroll
            for (int j2 = 0; j2 < 5; j2++) {
                double s = A[1 + j2] - ((j2 < 4) ? A[2 + j2] : 0.0);   // T_j - T_{j+1}
                double c = A[6 + j2] - ((j2 < 4) ? A[7 + j2] : 0.0);   // C_j - C_{j+1}
                double b = s / fmax(c, 1.0);
                double b2 = (c > 0.0) ? b * b : 0.0;
                m = fmax(m, b2);
            }
            m = fmax(m, 0.0);
            out[0] = (float)(mse_d + 5.0 * m);

#pragma unroll
            for (int k = 0; k < 11; k++) g_acc[k] = 0.0;
            __threadfence();
            g_ticket = 0u;
        }
    }
}

extern "C" void kernel_launch(void* const* d_in, const int* in_sizes, int n_in,
                              void* d_out, int out_size) {
    const float* y_pred = (const float*)d_in[0];
    const float* y_true = (const float*)d_in[1];
    const float* quants = (const float*)d_in[2];
    float* out = (float*)d_out;
    const int n = in_sizes[0];

    static bool attr_set = false;
    if (!attr_set) {
        cudaFuncSetAttribute(fused_loss_kernel,
                             cudaFuncAttributeMaxDynamicSharedMemorySize, SMEM_DYN);
        attr_set = true;
    }
    fused_loss_kernel<<<GRID, TPB, SMEM_DYN>>>(y_pred, y_true, quants, out, n);
}

// round 7
// speedup vs baseline: 1.0569x; 1.0569x over previous
#include <cuda_runtime.h>

// Cumulative accumulators: [0]=sum(d^2), [1..5]=T0..T4, [6..10]=C0..C4
__device__ double g_acc[11];
__device__ unsigned int g_ticket;

#define BLOCKS_PER_SM 5
#define GRID (148 * BLOCKS_PER_SM)   // 740, one full wave
#define TPB  256
#define BMAG 1024.0f                 // count-fusion magnitude (power of 2)

__global__ void __launch_bounds__(TPB, BLOCKS_PER_SM)
fused_loss_kernel(const float* __restrict__ y_pred,
                  const float* __restrict__ y_true,
                  const float* __restrict__ quants,
                  float* __restrict__ out, int n)
{
    const float q0 = quants[0], q1 = quants[1], q2 = quants[2];
    const float q3 = quants[3], q4 = quants[4], q5 = quants[5];

    float mse = 0.0f;
    // fused cumulative accumulators: U_k = T_k + BMAG * C_k
    float U0 = 0, U1 = 0, U2 = 0, U3 = 0, U4 = 0;

    const int stride = GRID * TPB;
    const int tid    = blockIdx.x * TPB + threadIdx.x;
    const int n4     = n >> 2;
    const float4* __restrict__ p4 = (const float4*)y_pred;
    const float4* __restrict__ t4 = (const float4*)y_true;

// w_k = (t >= q_k) & (t <= q5) as 0/1 float (FSET); U_k += w_k * (d + B).
// Exact searchsorted-right semantics (closed last bin via hi; out-of-range -> all w=0).
#define PR(p_, t_)                                        \
    do {                                                  \
        float t = (t_);                                   \
        float d = (p_)-t;                                 \
        mse = fmaf(d, d, mse);                            \
        float e = d + BMAG;                               \
        bool hi = (t <= q5);                              \
        float w0 = ((t >= q0) & hi) ? 1.0f : 0.0f;        \
        float w1 = ((t >= q1) & hi) ? 1.0f : 0.0f;        \
        float w2 = ((t >= q2) & hi) ? 1.0f : 0.0f;        \
        float w3 = ((t >= q3) & hi) ? 1.0f : 0.0f;        \
        float w4 = ((t >= q4) & hi) ? 1.0f : 0.0f;        \
        U0 = fmaf(w0, e, U0);                             \
        U1 = fmaf(w1, e, U1);                             \
        U2 = fmaf(w2, e, U2);                             \
        U3 = fmaf(w3, e, U3);                             \
        U4 = fmaf(w4, e, U4);                             \
    } while (0)

    int i = tid;
    // three float4-pairs per iteration: 6 front-loaded LDG.128 (MLP=6)
    for (; i + 2 * stride < n4; i += 3 * stride) {
        float4 pa = p4[i];
        float4 pb = p4[i + stride];
        float4 pc = p4[i + 2 * stride];
        float4 ta = t4[i];
        float4 tb = t4[i + stride];
        float4 tc = t4[i + 2 * stride];
        PR(pa.x, ta.x); PR(pa.y, ta.y); PR(pa.z, ta.z); PR(pa.w, ta.w);
        PR(pb.x, tb.x); PR(pb.y, tb.y); PR(pb.z, tb.z); PR(pb.w, tb.w);
        PR(pc.x, tc.x); PR(pc.y, tc.y); PR(pc.z, tc.z); PR(pc.w, tc.w);
    }
    for (; i < n4; i += stride) {
        float4 pa = p4[i];
        float4 ta = t4[i];
        PR(pa.x, ta.x); PR(pa.y, ta.y); PR(pa.z, ta.z); PR(pa.w, ta.w);
    }
    for (int j = (n4 << 2) + tid; j < n; j += stride) {
        float p = y_pred[j];
        float t = y_true[j];
        PR(p, t);
    }
#undef PR

    // per-thread recovery: C = rint(U/B) (exact: |T| << B/2, C*B exact fp32),
    // T = U - B*C (exact subtraction of representables)
    float v[11];
    v[0] = mse;
    {
        float Us[5] = {U0, U1, U2, U3, U4};
#pragma unroll
        for (int k = 0; k < 5; k++) {
            float c = rintf(Us[k] * (1.0f / BMAG));
            v[1 + k] = fmaf(-BMAG, c, Us[k]);   // T_k
            v[6 + k] = c;                       // C_k
        }
    }

    // ---- block reduction of 11 partials ----
#pragma unroll
    for (int k = 0; k < 11; k++) {
#pragma unroll
        for (int off = 16; off > 0; off >>= 1)
            v[k] += __shfl_down_sync(0xFFFFFFFFu, v[k], off);
    }

    __shared__ float shred[TPB / 32][11];
    const int wid = threadIdx.x >> 5;
    const int lid = threadIdx.x & 31;
    if (lid == 0) {
#pragma unroll
        for (int k = 0; k < 11; k++) shred[wid][k] = v[k];
    }
    __syncthreads();

    if (threadIdx.x < 11) {
        float acc = 0.0f;
#pragma unroll
        for (int w = 0; w < TPB / 32; w++) acc += shred[w][threadIdx.x];
        atomicAdd(&g_acc[threadIdx.x], (double)acc);
    }

    // ---- last block finalizes and resets (graph-replay safe) ----
    __syncthreads();
    if (threadIdx.x == 0) {
        __threadfence();
        unsigned int ticket = atomicAdd(&g_ticket, 1u);
        if (ticket == GRID - 1) {
            double A[11];
#pragma unroll
            for (int k = 0; k < 11; k++) A[k] = atomicAdd(&g_acc[k], 0.0);

            double mse_d = A[0] / (double)n;
            double m = 0.0;
#pragma unroll
            for (int j = 0; j < 5; j++) {
                double s = A[1 + j] - ((j < 4) ? A[2 + j] : 0.0);   // T_j - T_{j+1}
                double c = A[6 + j] - ((j < 4) ? A[7 + j] : 0.0);   // C_j - C_{j+1}
                double b = s / fmax(c, 1.0);
                double b2 = (c > 0.0) ? b * b : 0.0;
                m = fmax(m, b2);
            }
            m = fmax(m, 0.0);
            out[0] = (float)(mse_d + 5.0 * m);

#pragma unroll
            for (int k = 0; k < 11; k++) g_acc[k] = 0.0;
            __threadfence();
            g_ticket = 0u;
        }
    }
}

extern "C" void kernel_launch(void* const* d_in, const int* in_sizes, int n_in,
                              void* d_out, int out_size) {
    const float* y_pred = (const float*)d_in[0];
    const float* y_true = (const float*)d_in[1];
    const float* quants = (const float*)d_in[2];
    float* out = (float*)d_out;
    const int n = in_sizes[0];

    fused_loss_kernel<<<GRID, TPB>>>(y_pred, y_true, quants, out, n);
}

// round 8
// speedup vs baseline: 1.0744x; 1.0165x over previous
#include <cuda_runtime.h>

// Cumulative accumulators: [0]=sum(d^2), [1..5]=T0..T4, [6..10]=C0..C4
__device__ double g_acc[11];
__device__ unsigned int g_ticket;

#define BLOCKS_PER_SM 5
#define GRID (148 * BLOCKS_PER_SM)   // 740, one full wave
#define TPB  256
#define BMAG 1024.0f                 // count-fusion magnitude (power of 2)

// w_k = (t >= q_k) AND (t <= q5), as 1.0f/0.0f via a single FSET.AND each.
// Returns the five weights for this element.
__device__ __forceinline__ void bin_weights(float t, float q0, float q1, float q2,
                                            float q3, float q4, float q5,
                                            float& w0, float& w1, float& w2,
                                            float& w3, float& w4)
{
    asm("{\n\t"
        ".reg .pred h;\n\t"
        "setp.le.f32 h, %5, %11;\n\t"
        "set.ge.and.f32.f32 %0, %5, %6, h;\n\t"
        "set.ge.and.f32.f32 %1, %5, %7, h;\n\t"
        "set.ge.and.f32.f32 %2, %5, %8, h;\n\t"
        "set.ge.and.f32.f32 %3, %5, %9, h;\n\t"
        "set.ge.and.f32.f32 %4, %5, %10, h;\n\t"
        "}"
        : "=f"(w0), "=f"(w1), "=f"(w2), "=f"(w3), "=f"(w4)
        : "f"(t), "f"(q0), "f"(q1), "f"(q2), "f"(q3), "f"(q4), "f"(q5));
}

__global__ void __launch_bounds__(TPB, BLOCKS_PER_SM)
fused_loss_kernel(const float* __restrict__ y_pred,
                  const float* __restrict__ y_true,
                  const float* __restrict__ quants,
                  float* __restrict__ out, int n)
{
    const float q0 = quants[0], q1 = quants[1], q2 = quants[2];
    const float q3 = quants[3], q4 = quants[4], q5 = quants[5];

    float mse = 0.0f;
    // fused cumulative accumulators: U_k = T_k + BMAG * C_k
    float U0 = 0, U1 = 0, U2 = 0, U3 = 0, U4 = 0;

    const int stride = GRID * TPB;
    const int tid    = blockIdx.x * TPB + threadIdx.x;
    const int n4     = n >> 2;
    const float4* __restrict__ p4 = (const float4*)y_pred;
    const float4* __restrict__ t4 = (const float4*)y_true;

// 14 SASS instrs/elem: SETP+5 FSET (alu), 6 FFMA + 2 FADD (fma).
#define PR(p_, t_)                                          \
    do {                                                    \
        float t = (t_);                                     \
        float d = (p_)-t;                                   \
        mse = fmaf(d, d, mse);                              \
        float e = d + BMAG;                                 \
        float w0, w1, w2, w3, w4;                           \
        bin_weights(t, q0, q1, q2, q3, q4, q5,              \
                    w0, w1, w2, w3, w4);                    \
        U0 = fmaf(w0, e, U0);                               \
        U1 = fmaf(w1, e, U1);                               \
        U2 = fmaf(w2, e, U2);                               \
        U3 = fmaf(w3, e, U3);                               \
        U4 = fmaf(w4, e, U4);                               \
    } while (0)

    int i = tid;
    // two float4-pairs per iteration: 4 front-loaded LDG.128 (MLP=4) — champion config
    for (; i + stride < n4; i += 2 * stride) {
        float4 pa = p4[i];
        float4 pb = p4[i + stride];
        float4 ta = t4[i];
        float4 tb = t4[i + stride];
        PR(pa.x, ta.x); PR(pa.y, ta.y); PR(pa.z, ta.z); PR(pa.w, ta.w);
        PR(pb.x, tb.x); PR(pb.y, tb.y); PR(pb.z, tb.z); PR(pb.w, tb.w);
    }
    for (; i < n4; i += stride) {
        float4 pa = p4[i];
        float4 ta = t4[i];
        PR(pa.x, ta.x); PR(pa.y, ta.y); PR(pa.z, ta.z); PR(pa.w, ta.w);
    }
    for (int j = (n4 << 2) + tid; j < n; j += stride) {
        float p = y_pred[j];
        float t = y_true[j];
        PR(p, t);
    }
#undef PR

    // per-thread recovery: C = rint(U/B) (exact: |T| << B/2, C*B exact fp32),
    // T = U - B*C
    float v[11];
    v[0] = mse;
    {
        float Us[5] = {U0, U1, U2, U3, U4};
#pragma unroll
        for (int k = 0; k < 5; k++) {
            float c = rintf(Us[k] * (1.0f / BMAG));
            v[1 + k] = fmaf(-BMAG, c, Us[k]);   // T_k
            v[6 + k] = c;                       // C_k
        }
    }

    // ---- block reduction of 11 partials ----
#pragma unroll
    for (int k = 0; k < 11; k++) {
#pragma unroll
        for (int off = 16; off > 0; off >>= 1)
            v[k] += __shfl_down_sync(0xFFFFFFFFu, v[k], off);
    }

    __shared__ float shred[TPB / 32][11];
    const int wid = threadIdx.x >> 5;
    const int lid = threadIdx.x & 31;
    if (lid == 0) {
#pragma unroll
        for (int k = 0; k < 11; k++) shred[wid][k] = v[k];
    }
    __syncthreads();

    if (threadIdx.x < 11) {
        float acc = 0.0f;
#pragma unroll
        for (int w = 0; w < TPB / 32; w++) acc += shred[w][threadIdx.x];
        atomicAdd(&g_acc[threadIdx.x], (double)acc);
    }

    // ---- last block finalizes and resets (graph-replay safe) ----
    __syncthreads();
    if (threadIdx.x == 0) {
        __threadfence();
        unsigned int ticket = atomicAdd(&g_ticket, 1u);
        if (ticket == GRID - 1) {
            double A[11];
#pragma unroll
            for (int k = 0; k < 11; k++) A[k] = atomicAdd(&g_acc[k], 0.0);

            double mse_d = A[0] / (double)n;
            double m = 0.0;
#pragma unroll
            for (int j = 0; j < 5; j++) {
                double s = A[1 + j] - ((j < 4) ? A[2 + j] : 0.0);   // T_j - T_{j+1}
                double c = A[6 + j] - ((j < 4) ? A[7 + j] : 0.0);   // C_j - C_{j+1}
                double b = s / fmax(c, 1.0);
                double b2 = (c > 0.0) ? b * b : 0.0;
                m = fmax(m, b2);
            }
            m = fmax(m, 0.0);
            out[0] = (float)(mse_d + 5.0 * m);

#pragma unroll
            for (int k = 0; k < 11; k++) g_acc[k] = 0.0;
            __threadfence();
            g_ticket = 0u;
        }
    }
}

extern "C" void kernel_launch(void* const* d_in, const int* in_sizes, int n_in,
                              void* d_out, int out_size) {
    const float* y_pred = (const float*)d_in[0];
    const float* y_true = (const float*)d_in[1];
    const float* quants = (const float*)d_in[2];
    float* out = (float*)d_out;
    const int n = in_sizes[0];

    fused_loss_kernel<<<GRID, TPB>>>(y_pred, y_true, quants, out, n);
}